// round 10
// baseline (speedup 1.0000x reference)
#include <cuda_runtime.h>
#include <cuda_bf16.h>
#include <cstdint>
#include <math.h>

// ---------------------------------------------------------------------------
// LocalWindowAttention via split-bf16 mma.sync GEMMs (plain-sm_100 ISA).
//   C = Ah*Bh + Ah*Bl + Al*Bh   (hi/lo bf16 split of fp32, fp32 accum)
// R10: operand-shared passes. Each K-tile loads {Ah,Al,Bh,Bl} ONCE and runs
// all 3 MMA passes from smem: 1.5x less smem-fill traffic / LDSM / cp.async,
// 64 barriers instead of 96. BK=16, 3 stages x 16KB = 48KB static smem
// (NO cudaFuncSetAttribute — _HX_ENFORCE forbids device-limit changes).
// Tile: BM=BN=128, 256 thr, warp tile 64x32. Splits merged into 1 launch.
// ---------------------------------------------------------------------------

#define BATCH   2
#define S_LEN   4096
#define DMODEL  1024
#define NHEAD   16
#define HDIM    64
#define WIN     16
#define LPAD    8

#define M_ROWS  (BATCH * S_LEN)          // 8192
#define ELEMS   (M_ROWS * DMODEL)        // 8,388,608
#define WELEMS  (DMODEL * DMODEL)        // 1,048,576

static __device__ float g_q[ELEMS];
static __device__ float g_k[ELEMS];
static __device__ float g_v[ELEMS];
static __device__ __align__(256) __nv_bfloat16 g_xh[ELEMS];
static __device__ __align__(256) __nv_bfloat16 g_xl[ELEMS];
static __device__ __align__(256) __nv_bfloat16 g_ah[ELEMS];
static __device__ __align__(256) __nv_bfloat16 g_al[ELEMS];
static __device__ __align__(256) __nv_bfloat16 g_wh[4][WELEMS];
static __device__ __align__(256) __nv_bfloat16 g_wl[4][WELEMS];

// ---------------------------------------------------------------------------
__device__ __forceinline__ uint32_t smem_u32(const void* p) {
    uint32_t a;
    asm("{ .reg .u64 t; cvta.to.shared.u64 t, %1; cvt.u32.u64 %0, t; }"
        : "=r"(a) : "l"(p));
    return a;
}
__device__ __forceinline__ void cp16(uint32_t sdst, const void* gsrc) {
    asm volatile("cp.async.cg.shared.global [%0], [%1], 16;" :: "r"(sdst), "l"(gsrc));
}
#define CP_COMMIT() asm volatile("cp.async.commit_group;" ::: "memory")
#define CP_WAIT(n)  asm volatile("cp.async.wait_group %0;" :: "n"(n) : "memory")

__device__ __forceinline__ void ldsm_x4(uint32_t* r, uint32_t addr) {
    asm volatile("ldmatrix.sync.aligned.m8n8.x4.shared.b16 {%0,%1,%2,%3}, [%4];"
                 : "=r"(r[0]), "=r"(r[1]), "=r"(r[2]), "=r"(r[3]) : "r"(addr));
}
__device__ __forceinline__ void mma_bf16(float* c, const uint32_t* a, const uint32_t* b) {
    asm volatile(
        "mma.sync.aligned.m16n8k16.row.col.f32.bf16.bf16.f32 "
        "{%0,%1,%2,%3}, {%4,%5,%6,%7}, {%8,%9}, {%0,%1,%2,%3};"
        : "+f"(c[0]), "+f"(c[1]), "+f"(c[2]), "+f"(c[3])
        : "r"(a[0]), "r"(a[1]), "r"(a[2]), "r"(a[3]), "r"(b[0]), "r"(b[1]));
}

// ---------------------------------------------------------------------------
// GEMM geometry: BK=16 (32B rows), XOR swizzle  chunk' = chunk ^ ((row>>2)&1)
//   8-row ldmatrix phases / cp.async wavefronts -> 8 distinct 16B slots per
//   128B line. Conflict-free.
// Stage: Ah @0 | Al @4K | Bh @8K | Bl @12K  (16KB); 3 stages = 48KB.
// ---------------------------------------------------------------------------
#define PITCHB  32
#define OPER_B  (128 * PITCHB)   // 4096
#define STAGE_B (4 * OPER_B)     // 16384
#define NSTAGE  3                // 49152 = 48KB static
#define NKT     64               // 1024 / 16
#define TPB     256

__device__ __forceinline__ void load_tile(uint32_t sb, int t, int m0, int n0,
                                          const __nv_bfloat16* Ah,
                                          const __nv_bfloat16* Al,
                                          const __nv_bfloat16* Bh,
                                          const __nv_bfloat16* Bl, int tid)
{
    const int kb = t * 32;                   // byte offset within 2048B gmem row
    const int row = tid >> 1, c = tid & 1;   // 128 rows x 2 chunks = 256 thr
    const uint32_t so = (uint32_t)(row * PITCHB + ((c ^ ((row >> 2) & 1)) << 4));
    const size_t goff = (size_t)row * 2048 + c * 16 + kb;
    const int buf = t - (t / NSTAGE) * NSTAGE;      // t % 3
    const uint32_t st = sb + buf * STAGE_B;
    cp16(st + so,              (const char*)Ah + (size_t)m0 * 2048 + goff);
    cp16(st + OPER_B + so,     (const char*)Al + (size_t)m0 * 2048 + goff);
    cp16(st + 2 * OPER_B + so, (const char*)Bh + (size_t)n0 * 2048 + goff);
    cp16(st + 3 * OPER_B + so, (const char*)Bl + (size_t)n0 * 2048 + goff);
}

__device__ __forceinline__ void gemm_body(const __nv_bfloat16* Ah,
                                          const __nv_bfloat16* Al,
                                          const __nv_bfloat16* Bh,
                                          const __nv_bfloat16* Bl,
                                          float* __restrict__ C)
{
    __shared__ __align__(16) unsigned char smem[NSTAGE * STAGE_B];  // 48KB
    const uint32_t sb = smem_u32(smem);

    const int tid  = threadIdx.x;
    const int lane = tid & 31, wid = tid >> 5;
    const int wm = wid & 1;                  // 2 warps along M: 64 rows each
    const int wn = wid >> 1;                 // 4 warps along N: 32 cols each
    const int m0 = blockIdx.y * 128, n0 = blockIdx.x * 128;

    // ldmatrix lane geometry. Swizzle bit = (row>>2)&1; row offsets added
    // below (mi*16, n2*16, warp offsets) don't touch bit 2, so it's a
    // per-lane constant folded into the chunk select.
    const int sw   = (lane >> 2) & 1;                 // bit2 of lane
    const int aRow = wm * 64 + (lane & 15);
    const uint32_t aCh = (uint32_t)((((lane >> 4) ^ sw) & 1) << 4);
    const int bRow = wn * 32 + (lane & 7) + ((lane >> 4) * 8);
    const uint32_t bCh = (uint32_t)(((((lane >> 3) & 1) ^ sw) & 1) << 4);

    float acc[4][4][4];
#pragma unroll
    for (int i = 0; i < 4; ++i)
#pragma unroll
        for (int j = 0; j < 4; ++j)
#pragma unroll
            for (int r = 0; r < 4; ++r) acc[i][j][r] = 0.0f;

    load_tile(sb, 0, m0, n0, Ah, Al, Bh, Bl, tid); CP_COMMIT();
    load_tile(sb, 1, m0, n0, Ah, Al, Bh, Bl, tid); CP_COMMIT();

    int buf = 0;   // kt % 3
    for (int kt = 0; kt < NKT; ++kt) {
        if (kt < NKT - 1) CP_WAIT(1);
        else              CP_WAIT(0);
        __syncthreads();   // tile kt resident; buffer (kt+2)%3 free (its last
                           // reader was compute kt-1, finished by this barrier)

        if (kt + 2 < NKT) {            // refill overlaps compute kt and kt+1
            load_tile(sb, kt + 2, m0, n0, Ah, Al, Bh, Bl, tid);
            CP_COMMIT();
        }

        const uint32_t st = sb + buf * STAGE_B;
        const uint32_t aA = st + aRow * PITCHB + aCh;           // Ah
        const uint32_t aL = aA + OPER_B;                        // Al
        const uint32_t bH = st + 2 * OPER_B + bRow * PITCHB + bCh;
        const uint32_t bL = bH + OPER_B;

        uint32_t ah[4][4], bh[2][4], bl[2][4];
#pragma unroll
        for (int mi = 0; mi < 4; ++mi) ldsm_x4(ah[mi], aA + mi * (16 * PITCHB));
#pragma unroll
        for (int n2 = 0; n2 < 2; ++n2) ldsm_x4(bh[n2], bH + n2 * (16 * PITCHB));
#pragma unroll
        for (int n2 = 0; n2 < 2; ++n2) ldsm_x4(bl[n2], bL + n2 * (16 * PITCHB));

#pragma unroll
        for (int mi = 0; mi < 4; ++mi)       // pass 1: Ah*Bh
#pragma unroll
            for (int ni = 0; ni < 4; ++ni)
                mma_bf16(acc[mi][ni], ah[mi], &bh[ni >> 1][(ni & 1) * 2]);
#pragma unroll
        for (int mi = 0; mi < 4; ++mi)       // pass 2: Ah*Bl
#pragma unroll
            for (int ni = 0; ni < 4; ++ni)
                mma_bf16(acc[mi][ni], ah[mi], &bl[ni >> 1][(ni & 1) * 2]);

        uint32_t al[4][4];                   // pass 3: Al*Bh (Ah frags dead)
#pragma unroll
        for (int mi = 0; mi < 4; ++mi) ldsm_x4(al[mi], aL + mi * (16 * PITCHB));
#pragma unroll
        for (int mi = 0; mi < 4; ++mi)
#pragma unroll
            for (int ni = 0; ni < 4; ++ni)
                mma_bf16(acc[mi][ni], al[mi], &bh[ni >> 1][(ni & 1) * 2]);

        if (++buf == NSTAGE) buf = 0;
    }

    // epilogue: direct fp32 stores (float2 per half-tile row)
#pragma unroll
    for (int mi = 0; mi < 4; ++mi) {
#pragma unroll
        for (int ni = 0; ni < 4; ++ni) {
            const int m = m0 + wm * 64 + mi * 16 + (lane >> 2);
            const int n = n0 + wn * 32 + ni * 8 + 2 * (lane & 3);
            *(float2*)&C[(size_t)m * DMODEL + n] =
                make_float2(acc[mi][ni][0], acc[mi][ni][1]);
            *(float2*)&C[(size_t)(m + 8) * DMODEL + n] =
                make_float2(acc[mi][ni][2], acc[mi][ni][3]);
        }
    }
}

__global__ __launch_bounds__(TPB, 2)
void k_qkv_mma()
{
    const int z = blockIdx.z;
    float* C = (z == 0) ? g_q : (z == 1) ? g_k : g_v;
    gemm_body(g_xh, g_xl, g_wh[z], g_wl[z], C);
}

__global__ __launch_bounds__(TPB, 2)
void k_out_mma(float* __restrict__ out)
{
    gemm_body(g_ah, g_al, g_wh[3], g_wl[3], out);
}

// ---------------------------------------------------------------------------
// fp32 -> (hi, lo) bf16 split — x and all four weights in ONE launch.
// blocks [0, 8192): x ; [8192, 12288): weights (1024 blocks each)
// ---------------------------------------------------------------------------
__global__ __launch_bounds__(256)
void k_split_all(const float* __restrict__ x,  const float* __restrict__ Wq,
                 const float* __restrict__ Wk, const float* __restrict__ Wv,
                 const float* __restrict__ Wo,
                 __nv_bfloat16* __restrict__ xh, __nv_bfloat16* __restrict__ xl,
                 __nv_bfloat16* __restrict__ wh, __nv_bfloat16* __restrict__ wl)
{
    const int bid = blockIdx.x;
    const float* src;
    __nv_bfloat16 *dh, *dl;
    int blk;
    if (bid < ELEMS / 1024) {
        src = x; dh = xh; dl = xl; blk = bid;
    } else {
        const int w = (bid - ELEMS / 1024) >> 10;          // 0..3
        blk = (bid - ELEMS / 1024) & 1023;
        src = (w == 0) ? Wq : (w == 1) ? Wk : (w == 2) ? Wv : Wo;
        dh = wh + (size_t)w * WELEMS;
        dl = wl + (size_t)w * WELEMS;
    }
    const int i = (blk * 256 + threadIdx.x) * 4;
    const float4 v = *(const float4*)(src + i);
    __nv_bfloat16 h0 = __float2bfloat16(v.x);
    __nv_bfloat16 h1 = __float2bfloat16(v.y);
    __nv_bfloat16 h2 = __float2bfloat16(v.z);
    __nv_bfloat16 h3 = __float2bfloat16(v.w);
    __nv_bfloat16 l0 = __float2bfloat16(v.x - __bfloat162float(h0));
    __nv_bfloat16 l1 = __float2bfloat16(v.y - __bfloat162float(h1));
    __nv_bfloat16 l2 = __float2bfloat16(v.z - __bfloat162float(h2));
    __nv_bfloat16 l3 = __float2bfloat16(v.w - __bfloat162float(h3));
    *(__nv_bfloat162*)(dh + i)     = __nv_bfloat162(h0, h1);
    *(__nv_bfloat162*)(dh + i + 2) = __nv_bfloat162(h2, h3);
    *(__nv_bfloat162*)(dl + i)     = __nv_bfloat162(l0, l1);
    *(__nv_bfloat162*)(dl + i + 2) = __nv_bfloat162(l2, l3);
}

// ---------------------------------------------------------------------------
// Windowed attention: one warp per (b, h, s); emits bf16 hi/lo split.
// ---------------------------------------------------------------------------
__global__ __launch_bounds__(256)
void k_attn()
{
    const int wg   = (int)((blockIdx.x * blockDim.x + threadIdx.x) >> 5);
    const int lane = threadIdx.x & 31;

    const int s = wg & (S_LEN - 1);
    const int h = (wg >> 12) & (NHEAD - 1);
    const int b = wg >> 16;

    const size_t rowbase = ((size_t)(b * S_LEN + s)) * DMODEL + h * HDIM;
    const float2 qv = *(const float2*)(g_q + rowbase + 2 * lane);

    float sc[WIN];
#pragma unroll
    for (int j = 0; j < WIN; ++j) {
        const int sp = s + j - LPAD;
        float val = -1e30f;
        if (sp >= 0 && sp < S_LEN) {
            const size_t kb = ((size_t)(b * S_LEN + sp)) * DMODEL + h * HDIM;
            const float2 kv = *(const float2*)(g_k + kb + 2 * lane);
            float p = qv.x * kv.x + qv.y * kv.y;
            p += __shfl_xor_sync(0xffffffffu, p, 16);
            p += __shfl_xor_sync(0xffffffffu, p, 8);
            p += __shfl_xor_sync(0xffffffffu, p, 4);
            p += __shfl_xor_sync(0xffffffffu, p, 2);
            p += __shfl_xor_sync(0xffffffffu, p, 1);
            val = p * 0.125f;   // 1/sqrt(64)
        }
        sc[j] = val;
    }

    float mx = sc[0];
#pragma unroll
    for (int j = 1; j < WIN; ++j) mx = fmaxf(mx, sc[j]);

    float den = 0.0f, ax = 0.0f, ay = 0.0f;
#pragma unroll
    for (int j = 0; j < WIN; ++j) {
        const int sp = s + j - LPAD;
        if (sp >= 0 && sp < S_LEN) {
            const float p = __expf(sc[j] - mx);
            den += p;
            const size_t vb = ((size_t)(b * S_LEN + sp)) * DMODEL + h * HDIM;
            const float2 vv = *(const float2*)(g_v + vb + 2 * lane);
            ax = fmaf(p, vv.x, ax);
            ay = fmaf(p, vv.y, ay);
        }
    }
    const float inv = 1.0f / den;
    const float ox = ax * inv, oy = ay * inv;
    const __nv_bfloat16 hx = __float2bfloat16(ox);
    const __nv_bfloat16 hy = __float2bfloat16(oy);
    const __nv_bfloat16 lx = __float2bfloat16(ox - __bfloat162float(hx));
    const __nv_bfloat16 ly = __float2bfloat16(oy - __bfloat162float(hy));
    *(__nv_bfloat162*)(g_ah + rowbase + 2 * lane) = __nv_bfloat162(hx, hy);
    *(__nv_bfloat162*)(g_al + rowbase + 2 * lane) = __nv_bfloat162(lx, ly);
}

// ---------------------------------------------------------------------------
extern "C" void kernel_launch(void* const* d_in, const int* in_sizes, int n_in,
                              void* d_out, int out_size)
{
    (void)in_sizes; (void)n_in; (void)out_size;
    const float* x  = (const float*)d_in[0];
    const float* Wq = (const float*)d_in[1];
    const float* Wk = (const float*)d_in[2];
    const float* Wv = (const float*)d_in[3];
    const float* Wo = (const float*)d_in[4];
    float* out = (float*)d_out;

    // NOTE: no cudaFuncSetAttribute anywhere — smem static and <= 48KB.
    __nv_bfloat16 *xh, *xl, *wh, *wl;
    cudaGetSymbolAddress((void**)&xh, g_xh);
    cudaGetSymbolAddress((void**)&xl, g_xl);
    cudaGetSymbolAddress((void**)&wh, g_wh);
    cudaGetSymbolAddress((void**)&wl, g_wl);

    k_split_all<<<ELEMS / 1024 + 4 * (WELEMS / 1024), 256>>>(
        x, Wq, Wk, Wv, Wo, xh, xl, wh, wl);

    k_qkv_mma<<<dim3(8, 64, 3), TPB>>>();

    const int total_warps = BATCH * NHEAD * S_LEN;          // 131072
    k_attn<<<total_warps / 8, 256>>>();

    k_out_mma<<<dim3(8, 64), TPB>>>(out);
}

// round 11
// speedup vs baseline: 1.0005x; 1.0005x over previous
#include <cuda_runtime.h>
#include <cuda_bf16.h>
#include <cstdint>
#include <math.h>

// ---------------------------------------------------------------------------
// LocalWindowAttention via split-bf16 mma.sync GEMMs (plain-sm_100 ISA).
//   C = Ah*Bh + Ah*Bl + Al*Bh   (hi/lo bf16 split of fp32, fp32 accum)
// R11: R10's operand-shared passes + register-liveness fix. B fragments
// (bh,bl) hoisted once per K-tile; A streamed one row-fragment at a time
// (ldsm -> 8 or 4 dependent MMAs). Peak frag liveness ~24 regs vs R10's 48,
// so no spills at the launch_bounds(256,2) 128-reg cap.
// BK=16, 3 stages x 16KB = 48KB static smem. NO cudaFuncSetAttribute.
// ---------------------------------------------------------------------------

#define BATCH   2
#define S_LEN   4096
#define DMODEL  1024
#define NHEAD   16
#define HDIM    64
#define WIN     16
#define LPAD    8

#define M_ROWS  (BATCH * S_LEN)          // 8192
#define ELEMS   (M_ROWS * DMODEL)        // 8,388,608
#define WELEMS  (DMODEL * DMODEL)        // 1,048,576

static __device__ float g_q[ELEMS];
static __device__ float g_k[ELEMS];
static __device__ float g_v[ELEMS];
static __device__ __align__(256) __nv_bfloat16 g_xh[ELEMS];
static __device__ __align__(256) __nv_bfloat16 g_xl[ELEMS];
static __device__ __align__(256) __nv_bfloat16 g_ah[ELEMS];
static __device__ __align__(256) __nv_bfloat16 g_al[ELEMS];
static __device__ __align__(256) __nv_bfloat16 g_wh[4][WELEMS];
static __device__ __align__(256) __nv_bfloat16 g_wl[4][WELEMS];

// ---------------------------------------------------------------------------
__device__ __forceinline__ uint32_t smem_u32(const void* p) {
    uint32_t a;
    asm("{ .reg .u64 t; cvta.to.shared.u64 t, %1; cvt.u32.u64 %0, t; }"
        : "=r"(a) : "l"(p));
    return a;
}
__device__ __forceinline__ void cp16(uint32_t sdst, const void* gsrc) {
    asm volatile("cp.async.cg.shared.global [%0], [%1], 16;" :: "r"(sdst), "l"(gsrc));
}
#define CP_COMMIT() asm volatile("cp.async.commit_group;" ::: "memory")
#define CP_WAIT(n)  asm volatile("cp.async.wait_group %0;" :: "n"(n) : "memory")

__device__ __forceinline__ void ldsm_x4(uint32_t* r, uint32_t addr) {
    asm volatile("ldmatrix.sync.aligned.m8n8.x4.shared.b16 {%0,%1,%2,%3}, [%4];"
                 : "=r"(r[0]), "=r"(r[1]), "=r"(r[2]), "=r"(r[3]) : "r"(addr));
}
__device__ __forceinline__ void mma_bf16(float* c, const uint32_t* a, const uint32_t* b) {
    asm volatile(
        "mma.sync.aligned.m16n8k16.row.col.f32.bf16.bf16.f32 "
        "{%0,%1,%2,%3}, {%4,%5,%6,%7}, {%8,%9}, {%0,%1,%2,%3};"
        : "+f"(c[0]), "+f"(c[1]), "+f"(c[2]), "+f"(c[3])
        : "r"(a[0]), "r"(a[1]), "r"(a[2]), "r"(a[3]), "r"(b[0]), "r"(b[1]));
}

// ---------------------------------------------------------------------------
// GEMM geometry: BK=16 (32B rows), XOR swizzle  chunk' = chunk ^ ((row>>2)&1)
// Stage: Ah @0 | Al @4K | Bh @8K | Bl @12K  (16KB); 3 stages = 48KB.
// ---------------------------------------------------------------------------
#define PITCHB  32
#define OPER_B  (128 * PITCHB)   // 4096
#define STAGE_B (4 * OPER_B)     // 16384
#define NSTAGE  3                // 49152 = 48KB static
#define NKT     64               // 1024 / 16
#define TPB     256

__device__ __forceinline__ void load_tile(uint32_t sb, int t, int m0, int n0,
                                          const __nv_bfloat16* Ah,
                                          const __nv_bfloat16* Al,
                                          const __nv_bfloat16* Bh,
                                          const __nv_bfloat16* Bl, int tid)
{
    const int kb = t * 32;                   // byte offset within 2048B gmem row
    const int row = tid >> 1, c = tid & 1;   // 128 rows x 2 chunks = 256 thr
    const uint32_t so = (uint32_t)(row * PITCHB + ((c ^ ((row >> 2) & 1)) << 4));
    const size_t goff = (size_t)row * 2048 + c * 16 + kb;
    const int buf = t - (t / NSTAGE) * NSTAGE;      // t % 3
    const uint32_t st = sb + buf * STAGE_B;
    cp16(st + so,              (const char*)Ah + (size_t)m0 * 2048 + goff);
    cp16(st + OPER_B + so,     (const char*)Al + (size_t)m0 * 2048 + goff);
    cp16(st + 2 * OPER_B + so, (const char*)Bh + (size_t)n0 * 2048 + goff);
    cp16(st + 3 * OPER_B + so, (const char*)Bl + (size_t)n0 * 2048 + goff);
}

__device__ __forceinline__ void gemm_body(const __nv_bfloat16* Ah,
                                          const __nv_bfloat16* Al,
                                          const __nv_bfloat16* Bh,
                                          const __nv_bfloat16* Bl,
                                          float* __restrict__ C)
{
    __shared__ __align__(16) unsigned char smem[NSTAGE * STAGE_B];  // 48KB
    const uint32_t sb = smem_u32(smem);

    const int tid  = threadIdx.x;
    const int lane = tid & 31, wid = tid >> 5;
    const int wm = wid & 1;                  // 2 warps along M: 64 rows each
    const int wn = wid >> 1;                 // 4 warps along N: 32 cols each
    const int m0 = blockIdx.y * 128, n0 = blockIdx.x * 128;

    // ldmatrix lane geometry (swizzle bit (row>>2)&1 is a per-lane constant:
    // added row offsets are multiples of 8).
    const int sw   = (lane >> 2) & 1;
    const int aRow = wm * 64 + (lane & 15);
    const uint32_t aCh = (uint32_t)((((lane >> 4) ^ sw) & 1) << 4);
    const int bRow = wn * 32 + (lane & 7) + ((lane >> 4) * 8);
    const uint32_t bCh = (uint32_t)(((((lane >> 3) & 1) ^ sw) & 1) << 4);

    float acc[4][4][4];
#pragma unroll
    for (int i = 0; i < 4; ++i)
#pragma unroll
        for (int j = 0; j < 4; ++j)
#pragma unroll
            for (int r = 0; r < 4; ++r) acc[i][j][r] = 0.0f;

    load_tile(sb, 0, m0, n0, Ah, Al, Bh, Bl, tid); CP_COMMIT();
    load_tile(sb, 1, m0, n0, Ah, Al, Bh, Bl, tid); CP_COMMIT();

    int buf = 0;   // kt % 3
    for (int kt = 0; kt < NKT; ++kt) {
        if (kt < NKT - 1) CP_WAIT(1);
        else              CP_WAIT(0);
        __syncthreads();   // tile kt resident; buffer (kt+2)%3 free

        if (kt + 2 < NKT) {            // refill overlaps compute kt and kt+1
            load_tile(sb, kt + 2, m0, n0, Ah, Al, Bh, Bl, tid);
            CP_COMMIT();
        }

        const uint32_t st = sb + buf * STAGE_B;
        const uint32_t aA = st + aRow * PITCHB + aCh;           // Ah
        const uint32_t aL = aA + OPER_B;                        // Al
        const uint32_t bH = st + 2 * OPER_B + bRow * PITCHB + bCh;
        const uint32_t bL = bH + OPER_B;

        // B fragments hoisted once (16 regs, live whole iteration)
        uint32_t bh[2][4], bl[2][4];
#pragma unroll
        for (int n2 = 0; n2 < 2; ++n2) ldsm_x4(bh[n2], bH + n2 * (16 * PITCHB));
#pragma unroll
        for (int n2 = 0; n2 < 2; ++n2) ldsm_x4(bl[n2], bL + n2 * (16 * PITCHB));

        // A streamed one row-fragment at a time: ldsm -> 8 MMAs (pass1+2)
#pragma unroll
        for (int mi = 0; mi < 4; ++mi) {
            uint32_t ah[4];
            ldsm_x4(ah, aA + mi * (16 * PITCHB));
#pragma unroll
            for (int ni = 0; ni < 4; ++ni)       // pass 1: Ah*Bh
                mma_bf16(acc[mi][ni], ah, &bh[ni >> 1][(ni & 1) * 2]);
#pragma unroll
            for (int ni = 0; ni < 4; ++ni)       // pass 2: Ah*Bl
                mma_bf16(acc[mi][ni], ah, &bl[ni >> 1][(ni & 1) * 2]);
        }
        // pass 3: Al*Bh, same streaming pattern
#pragma unroll
        for (int mi = 0; mi < 4; ++mi) {
            uint32_t al[4];
            ldsm_x4(al, aL + mi * (16 * PITCHB));
#pragma unroll
            for (int ni = 0; ni < 4; ++ni)
                mma_bf16(acc[mi][ni], al, &bh[ni >> 1][(ni & 1) * 2]);
        }

        if (++buf == NSTAGE) buf = 0;
    }

    // epilogue: direct fp32 stores (float2 per half-tile row)
#pragma unroll
    for (int mi = 0; mi < 4; ++mi) {
#pragma unroll
        for (int ni = 0; ni < 4; ++ni) {
            const int m = m0 + wm * 64 + mi * 16 + (lane >> 2);
            const int n = n0 + wn * 32 + ni * 8 + 2 * (lane & 3);
            *(float2*)&C[(size_t)m * DMODEL + n] =
                make_float2(acc[mi][ni][0], acc[mi][ni][1]);
            *(float2*)&C[(size_t)(m + 8) * DMODEL + n] =
                make_float2(acc[mi][ni][2], acc[mi][ni][3]);
        }
    }
}

__global__ __launch_bounds__(TPB, 2)
void k_qkv_mma()
{
    const int z = blockIdx.z;
    float* C = (z == 0) ? g_q : (z == 1) ? g_k : g_v;
    gemm_body(g_xh, g_xl, g_wh[z], g_wl[z], C);
}

__global__ __launch_bounds__(TPB, 2)
void k_out_mma(float* __restrict__ out)
{
    gemm_body(g_ah, g_al, g_wh[3], g_wl[3], out);
}

// ---------------------------------------------------------------------------
// fp32 -> (hi, lo) bf16 split — x and all four weights in ONE launch.
// ---------------------------------------------------------------------------
__global__ __launch_bounds__(256)
void k_split_all(const float* __restrict__ x,  const float* __restrict__ Wq,
                 const float* __restrict__ Wk, const float* __restrict__ Wv,
                 const float* __restrict__ Wo,
                 __nv_bfloat16* __restrict__ xh, __nv_bfloat16* __restrict__ xl,
                 __nv_bfloat16* __restrict__ wh, __nv_bfloat16* __restrict__ wl)
{
    const int bid = blockIdx.x;
    const float* src;
    __nv_bfloat16 *dh, *dl;
    int blk;
    if (bid < ELEMS / 1024) {
        src = x; dh = xh; dl = xl; blk = bid;
    } else {
        const int w = (bid - ELEMS / 1024) >> 10;          // 0..3
        blk = (bid - ELEMS / 1024) & 1023;
        src = (w == 0) ? Wq : (w == 1) ? Wk : (w == 2) ? Wv : Wo;
        dh = wh + (size_t)w * WELEMS;
        dl = wl + (size_t)w * WELEMS;
    }
    const int i = (blk * 256 + threadIdx.x) * 4;
    const float4 v = *(const float4*)(src + i);
    __nv_bfloat16 h0 = __float2bfloat16(v.x);
    __nv_bfloat16 h1 = __float2bfloat16(v.y);
    __nv_bfloat16 h2 = __float2bfloat16(v.z);
    __nv_bfloat16 h3 = __float2bfloat16(v.w);
    __nv_bfloat16 l0 = __float2bfloat16(v.x - __bfloat162float(h0));
    __nv_bfloat16 l1 = __float2bfloat16(v.y - __bfloat162float(h1));
    __nv_bfloat16 l2 = __float2bfloat16(v.z - __bfloat162float(h2));
    __nv_bfloat16 l3 = __float2bfloat16(v.w - __bfloat162float(h3));
    *(__nv_bfloat162*)(dh + i)     = __nv_bfloat162(h0, h1);
    *(__nv_bfloat162*)(dh + i + 2) = __nv_bfloat162(h2, h3);
    *(__nv_bfloat162*)(dl + i)     = __nv_bfloat162(l0, l1);
    *(__nv_bfloat162*)(dl + i + 2) = __nv_bfloat162(l2, l3);
}

// ---------------------------------------------------------------------------
// Windowed attention: one warp per (b, h, s); emits bf16 hi/lo split.
// ---------------------------------------------------------------------------
__global__ __launch_bounds__(256)
void k_attn()
{
    const int wg   = (int)((blockIdx.x * blockDim.x + threadIdx.x) >> 5);
    const int lane = threadIdx.x & 31;

    const int s = wg & (S_LEN - 1);
    const int h = (wg >> 12) & (NHEAD - 1);
    const int b = wg >> 16;

    const size_t rowbase = ((size_t)(b * S_LEN + s)) * DMODEL + h * HDIM;
    const float2 qv = *(const float2*)(g_q + rowbase + 2 * lane);

    float sc[WIN];
#pragma unroll
    for (int j = 0; j < WIN; ++j) {
        const int sp = s + j - LPAD;
        float val = -1e30f;
        if (sp >= 0 && sp < S_LEN) {
            const size_t kb = ((size_t)(b * S_LEN + sp)) * DMODEL + h * HDIM;
            const float2 kv = *(const float2*)(g_k + kb + 2 * lane);
            float p = qv.x * kv.x + qv.y * kv.y;
            p += __shfl_xor_sync(0xffffffffu, p, 16);
            p += __shfl_xor_sync(0xffffffffu, p, 8);
            p += __shfl_xor_sync(0xffffffffu, p, 4);
            p += __shfl_xor_sync(0xffffffffu, p, 2);
            p += __shfl_xor_sync(0xffffffffu, p, 1);
            val = p * 0.125f;   // 1/sqrt(64)
        }
        sc[j] = val;
    }

    float mx = sc[0];
#pragma unroll
    for (int j = 1; j < WIN; ++j) mx = fmaxf(mx, sc[j]);

    float den = 0.0f, ax = 0.0f, ay = 0.0f;
#pragma unroll
    for (int j = 0; j < WIN; ++j) {
        const int sp = s + j - LPAD;
        if (sp >= 0 && sp < S_LEN) {
            const float p = __expf(sc[j] - mx);
            den += p;
            const size_t vb = ((size_t)(b * S_LEN + sp)) * DMODEL + h * HDIM;
            const float2 vv = *(const float2*)(g_v + vb + 2 * lane);
            ax = fmaf(p, vv.x, ax);
            ay = fmaf(p, vv.y, ay);
        }
    }
    const float inv = 1.0f / den;
    const float ox = ax * inv, oy = ay * inv;
    const __nv_bfloat16 hx = __float2bfloat16(ox);
    const __nv_bfloat16 hy = __float2bfloat16(oy);
    const __nv_bfloat16 lx = __float2bfloat16(ox - __bfloat162float(hx));
    const __nv_bfloat16 ly = __float2bfloat16(oy - __bfloat162float(hy));
    *(__nv_bfloat162*)(g_ah + rowbase + 2 * lane) = __nv_bfloat162(hx, hy);
    *(__nv_bfloat162*)(g_al + rowbase + 2 * lane) = __nv_bfloat162(lx, ly);
}

// ---------------------------------------------------------------------------
extern "C" void kernel_launch(void* const* d_in, const int* in_sizes, int n_in,
                              void* d_out, int out_size)
{
    (void)in_sizes; (void)n_in; (void)out_size;
    const float* x  = (const float*)d_in[0];
    const float* Wq = (const float*)d_in[1];
    const float* Wk = (const float*)d_in[2];
    const float* Wv = (const float*)d_in[3];
    const float* Wo = (const float*)d_in[4];
    float* out = (float*)d_out;

    // NOTE: no cudaFuncSetAttribute anywhere — smem static and <= 48KB.
    __nv_bfloat16 *xh, *xl, *wh, *wl;
    cudaGetSymbolAddress((void**)&xh, g_xh);
    cudaGetSymbolAddress((void**)&xl, g_xl);
    cudaGetSymbolAddress((void**)&wh, g_wh);
    cudaGetSymbolAddress((void**)&wl, g_wl);

    k_split_all<<<ELEMS / 1024 + 4 * (WELEMS / 1024), 256>>>(
        x, Wq, Wk, Wv, Wo, xh, xl, wh, wl);

    k_qkv_mma<<<dim3(8, 64, 3), TPB>>>();

    const int total_warps = BATCH * NHEAD * S_LEN;          // 131072
    k_attn<<<total_warps / 8, 256>>>();

    k_out_mma<<<dim3(8, 64), TPB>>>(out);
}